// round 8
// baseline (speedup 1.0000x reference)
#include <cuda_runtime.h>
#include <cstdint>

// Problem constants
#define N_NODES 16384
#define KNBR    32
#define DIN     256
#define DOUT    256
#define DCAT    512
#define NROWS   (N_NODES * KNBR)   // 524288

// ---------------------------------------------------------------------------
// Scratch (static device globals — no runtime allocation)
// ---------------------------------------------------------------------------
__device__ float g_Q[N_NODES * DOUT];          // 16 MB
__device__ float g_KV[268435456];              // NROWS*DCAT = 1 GB: per row [keys(256) | values(256)]
__device__ float g_rowsum[NROWS];              // 2 MB
__device__ float g_ctx[N_NODES * DOUT];        // 16 MB
__device__ float g_ob[N_NODES * DCAT];         // 32 MB  output = [self_out | neigh_out]
__device__ float g_gate[N_NODES * DCAT];       // 32 MB
__device__ float g_Wkv[DCAT * DIN];
__device__ float g_bkv[DCAT];
__device__ float g_psum[128 * DCAT];
__device__ float g_psq[128 * DCAT];
__device__ float g_mean[DCAT];
__device__ float g_rstd[DCAT];

// ---------------------------------------------------------------------------
// Packed fp32x2 helpers (Blackwell FFMA2 path: 2x throughput vs 3-reg FFMA)
// ---------------------------------------------------------------------------
__device__ __forceinline__ unsigned long long pack2(float x) {
    unsigned long long r;
    asm("mov.b64 %0, {%1, %1};" : "=l"(r) : "r"(__float_as_uint(x)));
    return r;
}

__device__ __forceinline__ void ffma2(unsigned long long& c,
                                      unsigned long long a,
                                      unsigned long long b) {
    asm("fma.rn.f32x2 %0, %1, %2, %0;" : "+l"(c) : "l"(a), "l"(b));
}

// ---------------------------------------------------------------------------
// Tiled SGEMM: C[m][n] = sum_k A[m][k] * W[n][k] + bias[n]   (A: MxK, W: NxK)
// BM=BN=128, BK=16, 256 threads, 8x8 per thread, fp32x2 accumulators.
// Requires M,N multiples of 128 and K multiple of 16 (true for all calls).
// ---------------------------------------------------------------------------
template <bool RELU>
__global__ void __launch_bounds__(256, 2)
sgemm_kernel(const float* __restrict__ A, const float* __restrict__ W,
             const float* __restrict__ bias, float* __restrict__ C,
             int K, int ldc)
{
    __shared__ float As[16][128];
    __shared__ float Bs[16][128];

    const int    tid = threadIdx.x;
    const size_t bm  = (size_t)blockIdx.y * 128;
    const int    bn  = blockIdx.x * 128;
    const int    tx  = tid & 15, ty = tid >> 4;
    const int    m0  = ty * 8,   n0 = tx * 8;
    const int    lr  = tid >> 2;          // 0..63
    const int    lk  = (tid & 3) * 4;     // 0,4,8,12

    unsigned long long acc[8][4];
#pragma unroll
    for (int i = 0; i < 8; i++)
#pragma unroll
        for (int j = 0; j < 4; j++) acc[i][j] = 0ull;

    for (int k0 = 0; k0 < K; k0 += 16) {
        float4 a0 = *(const float4*)(A + (bm + lr) * (size_t)K + k0 + lk);
        float4 a1 = *(const float4*)(A + (bm + lr + 64) * (size_t)K + k0 + lk);
        float4 w0 = *(const float4*)(W + (size_t)(bn + lr) * K + k0 + lk);
        float4 w1 = *(const float4*)(W + (size_t)(bn + lr + 64) * K + k0 + lk);
        __syncthreads();
        As[lk + 0][lr]      = a0.x; As[lk + 1][lr]      = a0.y;
        As[lk + 2][lr]      = a0.z; As[lk + 3][lr]      = a0.w;
        As[lk + 0][lr + 64] = a1.x; As[lk + 1][lr + 64] = a1.y;
        As[lk + 2][lr + 64] = a1.z; As[lk + 3][lr + 64] = a1.w;
        Bs[lk + 0][lr]      = w0.x; Bs[lk + 1][lr]      = w0.y;
        Bs[lk + 2][lr]      = w0.z; Bs[lk + 3][lr]      = w0.w;
        Bs[lk + 0][lr + 64] = w1.x; Bs[lk + 1][lr + 64] = w1.y;
        Bs[lk + 2][lr + 64] = w1.z; Bs[lk + 3][lr + 64] = w1.w;
        __syncthreads();

#pragma unroll
        for (int kk = 0; kk < 16; kk++) {
            float4 av0 = *(const float4*)&As[kk][m0];
            float4 av1 = *(const float4*)&As[kk][m0 + 4];
            ulonglong2 bq0 = *(const ulonglong2*)&Bs[kk][n0];
            ulonglong2 bq1 = *(const ulonglong2*)&Bs[kk][n0 + 4];
            const unsigned long long bp0 = bq0.x, bp1 = bq0.y;
            const unsigned long long bp2 = bq1.x, bp3 = bq1.y;
            float am[8] = {av0.x, av0.y, av0.z, av0.w, av1.x, av1.y, av1.z, av1.w};
#pragma unroll
            for (int i = 0; i < 8; i++) {
                unsigned long long ap = pack2(am[i]);
                ffma2(acc[i][0], ap, bp0);
                ffma2(acc[i][1], ap, bp1);
                ffma2(acc[i][2], ap, bp2);
                ffma2(acc[i][3], ap, bp3);
            }
        }
    }

    float bcol[8];
#pragma unroll
    for (int j = 0; j < 8; j++) bcol[j] = bias[bn + n0 + j];
#pragma unroll
    for (int i = 0; i < 8; i++) {
        float* crow = C + (bm + m0 + i) * (size_t)ldc + bn + n0;
#pragma unroll
        for (int j = 0; j < 4; j++) {
            float lo = __uint_as_float((unsigned)(acc[i][j] & 0xffffffffull)) + bcol[2 * j];
            float hi = __uint_as_float((unsigned)(acc[i][j] >> 32)) + bcol[2 * j + 1];
            if (RELU) { lo = fmaxf(lo, 0.f); hi = fmaxf(hi, 0.f); }
            crow[2 * j]     = lo;
            crow[2 * j + 1] = hi;
        }
    }
}

// ---------------------------------------------------------------------------
// Pack Wkv = [Wk ; Wv] (512 x 256), bkv = [bk ; bv]
// ---------------------------------------------------------------------------
__global__ void pack_wkv_kernel(const float* __restrict__ Wk, const float* __restrict__ bk,
                                const float* __restrict__ Wv, const float* __restrict__ bv,
                                float* __restrict__ Wkv, float* __restrict__ bkv)
{
    const int nrow = blockIdx.x;
    const int t    = threadIdx.x;
    const float* src = (nrow < DOUT) ? (Wk + (size_t)nrow * DIN)
                                     : (Wv + (size_t)(nrow - DOUT) * DIN);
    Wkv[(size_t)nrow * DIN + t] = src[t];
    if (t == 0) bkv[nrow] = (nrow < DOUT) ? bk[nrow] : bv[nrow - DOUT];
}

// ---------------------------------------------------------------------------
// Row sums of neighbor_inputs (for the exact ==0 padding mask)
// 8 rows per CTA, one warp per row.
// ---------------------------------------------------------------------------
__global__ void __launch_bounds__(256)
rowsum_kernel(const float* __restrict__ X, float* __restrict__ rs)
{
    const int row  = blockIdx.x * 8 + (threadIdx.x >> 5);
    const int lane = threadIdx.x & 31;
    const float4* p = (const float4*)(X + (size_t)row * DIN) + lane * 2;
    float4 v0 = p[0], v1 = p[1];
    float s = v0.x + v0.y + v0.z + v0.w + v1.x + v1.y + v1.z + v1.w;
#pragma unroll
    for (int o = 16; o; o >>= 1) s += __shfl_xor_sync(0xffffffffu, s, o);
    if (lane == 0) rs[row] = s;
}

// ---------------------------------------------------------------------------
// Fused attention: energies -> mask -> softmax -> context, one node per CTA
// ---------------------------------------------------------------------------
__global__ void __launch_bounds__(256)
attn_kernel(const float* __restrict__ Q, const float* __restrict__ KV,
            const float* __restrict__ rowsum, float* __restrict__ ctx)
{
    __shared__ float qs[256];
    __shared__ float es[32];
    __shared__ float att[32];
    const int n    = blockIdx.x;
    const int t    = threadIdx.x;
    const int lane = t & 31, w = t >> 5;

    qs[t] = Q[(size_t)n * DOUT + t];
    __syncthreads();

    // energies: 8 warps x 4 neighbors each
#pragma unroll
    for (int i = 0; i < 4; i++) {
        const int k = w * 4 + i;
        const float* kr = KV + ((size_t)n * KNBR + k) * DCAT + lane * 8;
        float4 k0 = *(const float4*)kr;
        float4 k1 = *(const float4*)(kr + 4);
        const float* qp = qs + lane * 8;
        float p = k0.x * qp[0] + k0.y * qp[1] + k0.z * qp[2] + k0.w * qp[3]
                + k1.x * qp[4] + k1.y * qp[5] + k1.z * qp[6] + k1.w * qp[7];
#pragma unroll
        for (int o = 16; o; o >>= 1) p += __shfl_xor_sync(0xffffffffu, p, o);
        if (lane == 0) es[k] = p;
    }
    __syncthreads();

    // softmax over K=32 (warp 0), masked positions forced to 1e-12 pre-softmax
    if (t < 32) {
        float e = es[t];
        if (rowsum[(size_t)n * KNBR + t] == 0.0f) e = 1e-12f;
        float m = e;
#pragma unroll
        for (int o = 16; o; o >>= 1) m = fmaxf(m, __shfl_xor_sync(0xffffffffu, m, o));
        float ex = expf(e - m);
        float s = ex;
#pragma unroll
        for (int o = 16; o; o >>= 1) s += __shfl_xor_sync(0xffffffffu, s, o);
        att[t] = ex / s;
    }
    __syncthreads();

    // context[d] = sum_k att[k] * values[n,k,d]   (values = KV cols 256..511)
    const float* vb = KV + (size_t)n * KNBR * DCAT + DOUT + t;
    float c = 0.f;
#pragma unroll
    for (int k = 0; k < KNBR; k++) c = fmaf(att[k], vb[(size_t)k * DCAT], c);
    ctx[(size_t)n * DOUT + t] = c;
}

// ---------------------------------------------------------------------------
// BatchNorm statistics: two-phase deterministic reduction
// ---------------------------------------------------------------------------
__global__ void __launch_bounds__(256)
bn_partial_kernel(const float* __restrict__ ob, float* __restrict__ psum,
                  float* __restrict__ psq)
{
    const int b = blockIdx.x, t = threadIdx.x;  // 128 blocks x 128 rows each
    float s0 = 0, s1 = 0, q0 = 0, q1 = 0;
    for (int r = 0; r < 128; r++) {
        const float* row = ob + ((size_t)b * 128 + r) * DCAT;
        float x0 = row[t], x1 = row[t + 256];
        s0 += x0; q0 += x0 * x0;
        s1 += x1; q1 += x1 * x1;
    }
    psum[b * DCAT + t]       = s0;
    psum[b * DCAT + t + 256] = s1;
    psq[b * DCAT + t]        = q0;
    psq[b * DCAT + t + 256]  = q1;
}

__global__ void bn_final_kernel(const float* __restrict__ psum, const float* __restrict__ psq,
                                float* __restrict__ mean, float* __restrict__ rstd)
{
    const int c = blockIdx.x * 256 + threadIdx.x;
    float s = 0, q = 0;
    for (int b = 0; b < 128; b++) { s += psum[b * DCAT + c]; q += psq[b * DCAT + c]; }
    float m = s / (float)N_NODES;
    float v = q / (float)N_NODES - m * m;   // biased variance (ddof=0)
    mean[c] = m;
    rstd[c] = rsqrtf(v + 1e-5f);
}

// ---------------------------------------------------------------------------
// Final elementwise: out = gate * relu(gamma*(output-mean)*rstd + beta)
// ---------------------------------------------------------------------------
__global__ void __launch_bounds__(256)
final_kernel(const float* __restrict__ ob, const float* __restrict__ gate,
             const float* __restrict__ mean, const float* __restrict__ rstd,
             const float* __restrict__ gamma, const float* __restrict__ beta,
             float* __restrict__ out)
{
    const size_t i = (size_t)blockIdx.x * 256 + threadIdx.x;   // float4 index
    const int    c = ((int)(i & 127)) * 4;
    float4 x = ((const float4*)ob)[i];
    float4 g = ((const float4*)gate)[i];
    float4 r;
    r.x = g.x * fmaxf(gamma[c + 0] * (x.x - mean[c + 0]) * rstd[c + 0] + beta[c + 0], 0.f);
    r.y = g.y * fmaxf(gamma[c + 1] * (x.y - mean[c + 1]) * rstd[c + 1] + beta[c + 1], 0.f);
    r.z = g.z * fmaxf(gamma[c + 2] * (x.z - mean[c + 2]) * rstd[c + 2] + beta[c + 2], 0.f);
    r.w = g.w * fmaxf(gamma[c + 3] * (x.w - mean[c + 3]) * rstd[c + 3] + beta[c + 3], 0.f);
    ((float4*)out)[i] = r;
}

// ---------------------------------------------------------------------------
// Launch
// ---------------------------------------------------------------------------
extern "C" void kernel_launch(void* const* d_in, const int* in_sizes, int n_in,
                              void* d_out, int out_size)
{
    const float* input = (const float*)d_in[0];
    const float* nbr   = (const float*)d_in[1];
    const float* Wq    = (const float*)d_in[2];
    const float* bq    = (const float*)d_in[3];
    const float* Wk    = (const float*)d_in[4];
    const float* bk    = (const float*)d_in[5];
    const float* Wv    = (const float*)d_in[6];
    const float* bv    = (const float*)d_in[7];
    const float* Wno   = (const float*)d_in[8];
    const float* bno   = (const float*)d_in[9];
    const float* Wio   = (const float*)d_in[10];
    const float* bio   = (const float*)d_in[11];
    const float* Wg    = (const float*)d_in[12];
    const float* bg    = (const float*)d_in[13];
    const float* gamma = (const float*)d_in[14];
    const float* beta  = (const float*)d_in[15];
    float* out = (float*)d_out;

    float *Qp, *KVp, *rsp, *ctxp, *obp, *gatep, *Wkvp, *bkvp, *psump, *psqp, *meanp, *rstdp;
    cudaGetSymbolAddress((void**)&Qp,    g_Q);
    cudaGetSymbolAddress((void**)&KVp,   g_KV);
    cudaGetSymbolAddress((void**)&rsp,   g_rowsum);
    cudaGetSymbolAddress((void**)&ctxp,  g_ctx);
    cudaGetSymbolAddress((void**)&obp,   g_ob);
    cudaGetSymbolAddress((void**)&gatep, g_gate);
    cudaGetSymbolAddress((void**)&Wkvp,  g_Wkv);
    cudaGetSymbolAddress((void**)&bkvp,  g_bkv);
    cudaGetSymbolAddress((void**)&psump, g_psum);
    cudaGetSymbolAddress((void**)&psqp,  g_psq);
    cudaGetSymbolAddress((void**)&meanp, g_mean);
    cudaGetSymbolAddress((void**)&rstdp, g_rstd);

    // Independent prep
    pack_wkv_kernel<<<DCAT, 256>>>(Wk, bk, Wv, bv, Wkvp, bkvp);
    rowsum_kernel<<<NROWS / 8, 256>>>(nbr, rsp);

    // queries = input @ Wq^T + bq
    sgemm_kernel<false><<<dim3(DOUT / 128, N_NODES / 128), 256>>>(input, Wq, bq, Qp, DIN, DOUT);
    // self_out = input @ Wio^T + bio  -> output[:, 0:256]
    sgemm_kernel<false><<<dim3(DOUT / 128, N_NODES / 128), 256>>>(input, Wio, bio, obp, DIN, DCAT);

    // keys|values = neighbor_inputs @ [Wk;Wv]^T + [bk;bv]   (the heavy GEMM)
    sgemm_kernel<false><<<dim3(DCAT / 128, NROWS / 128), 256>>>(nbr, Wkvp, bkvp, KVp, DIN, DCAT);

    // attention: energies -> mask -> softmax -> context
    attn_kernel<<<N_NODES, 256>>>(Qp, KVp, rsp, ctxp);

    // neigh_out = context @ Wno^T + bno -> output[:, 256:512]
    sgemm_kernel<false><<<dim3(DOUT / 128, N_NODES / 128), 256>>>(ctxp, Wno, bno, obp + 256, DOUT, DCAT);

    // gate = relu(output @ Wg^T + bg)
    sgemm_kernel<true><<<dim3(DCAT / 128, N_NODES / 128), 256>>>(obp, Wg, bg, gatep, DCAT, DCAT);

    // BatchNorm statistics (deterministic two-phase) + final elementwise
    bn_partial_kernel<<<128, 256>>>(obp, psump, psqp);
    bn_final_kernel<<<2, 256>>>(psump, psqp, meanp, rstdp);
    final_kernel<<<(N_NODES * DCAT / 4) / 256, 256>>>(obp, gatep, meanp, rstdp, gamma, beta, out);
}

// round 9
// speedup vs baseline: 1.0002x; 1.0002x over previous
#include <cuda_runtime.h>
#include <cstdint>

// Problem constants
#define N_NODES 16384
#define KNBR    32
#define DIN     256
#define DOUT    256
#define DCAT    512
#define NROWS   (N_NODES * KNBR)   // 524288

// ---------------------------------------------------------------------------
// Scratch (static device globals — no runtime allocation)
// ---------------------------------------------------------------------------
__device__ float g_Q[N_NODES * DOUT];          // 16 MB
__device__ float g_KV[268435456];              // NROWS*DCAT = 1 GB: per row [keys(256) | values(256)]
__device__ float g_rowsum[NROWS];              // 2 MB
__device__ float g_ctx[N_NODES * DOUT];        // 16 MB
__device__ float g_ob[N_NODES * DCAT];         // 32 MB  output = [self_out | neigh_out]
__device__ float g_gate[N_NODES * DCAT];       // 32 MB
__device__ float g_Wkv[DCAT * DIN];
__device__ float g_bkv[DCAT];
__device__ float g_psum[128 * DCAT];
__device__ float g_psq[128 * DCAT];
__device__ float g_mean[DCAT];
__device__ float g_rstd[DCAT];

// ---------------------------------------------------------------------------
// Packed fp32x2 helpers (Blackwell FFMA2 path: 2x throughput vs 3-reg FFMA)
// ---------------------------------------------------------------------------
__device__ __forceinline__ unsigned long long pack2(float x) {
    unsigned long long r;
    asm("mov.b64 %0, {%1, %1};" : "=l"(r) : "r"(__float_as_uint(x)));
    return r;
}

__device__ __forceinline__ void ffma2(unsigned long long& c,
                                      unsigned long long a,
                                      unsigned long long b) {
    asm("fma.rn.f32x2 %0, %1, %2, %0;" : "+l"(c) : "l"(a), "l"(b));
}

// ---------------------------------------------------------------------------
// Tiled SGEMM: C[m][n] = sum_k A[m][k] * W[n][k] + bias[n]   (A: MxK, W: NxK)
// BM=BN=128, BK=16, 256 threads, 8x8 per thread, fp32x2 accumulators.
// Requires M,N multiples of 128 and K multiple of 16 (true for all calls).
// ---------------------------------------------------------------------------
template <bool RELU>
__global__ void __launch_bounds__(256, 2)
sgemm_kernel(const float* __restrict__ A, const float* __restrict__ W,
             const float* __restrict__ bias, float* __restrict__ C,
             int K, int ldc)
{
    __shared__ float As[16][128];
    __shared__ float Bs[16][128];

    const int    tid = threadIdx.x;
    const size_t bm  = (size_t)blockIdx.y * 128;
    const int    bn  = blockIdx.x * 128;
    const int    tx  = tid & 15, ty = tid >> 4;
    const int    m0  = ty * 8,   n0 = tx * 8;
    const int    lr  = tid >> 2;          // 0..63
    const int    lk  = (tid & 3) * 4;     // 0,4,8,12

    unsigned long long acc[8][4];
#pragma unroll
    for (int i = 0; i < 8; i++)
#pragma unroll
        for (int j = 0; j < 4; j++) acc[i][j] = 0ull;

    for (int k0 = 0; k0 < K; k0 += 16) {
        float4 a0 = *(const float4*)(A + (bm + lr) * (size_t)K + k0 + lk);
        float4 a1 = *(const float4*)(A + (bm + lr + 64) * (size_t)K + k0 + lk);
        float4 w0 = *(const float4*)(W + (size_t)(bn + lr) * K + k0 + lk);
        float4 w1 = *(const float4*)(W + (size_t)(bn + lr + 64) * K + k0 + lk);
        __syncthreads();
        As[lk + 0][lr]      = a0.x; As[lk + 1][lr]      = a0.y;
        As[lk + 2][lr]      = a0.z; As[lk + 3][lr]      = a0.w;
        As[lk + 0][lr + 64] = a1.x; As[lk + 1][lr + 64] = a1.y;
        As[lk + 2][lr + 64] = a1.z; As[lk + 3][lr + 64] = a1.w;
        Bs[lk + 0][lr]      = w0.x; Bs[lk + 1][lr]      = w0.y;
        Bs[lk + 2][lr]      = w0.z; Bs[lk + 3][lr]      = w0.w;
        Bs[lk + 0][lr + 64] = w1.x; Bs[lk + 1][lr + 64] = w1.y;
        Bs[lk + 2][lr + 64] = w1.z; Bs[lk + 3][lr + 64] = w1.w;
        __syncthreads();

#pragma unroll
        for (int kk = 0; kk < 16; kk++) {
            float4 av0 = *(const float4*)&As[kk][m0];
            float4 av1 = *(const float4*)&As[kk][m0 + 4];
            ulonglong2 bq0 = *(const ulonglong2*)&Bs[kk][n0];
            ulonglong2 bq1 = *(const ulonglong2*)&Bs[kk][n0 + 4];
            const unsigned long long bp0 = bq0.x, bp1 = bq0.y;
            const unsigned long long bp2 = bq1.x, bp3 = bq1.y;
            float am[8] = {av0.x, av0.y, av0.z, av0.w, av1.x, av1.y, av1.z, av1.w};
#pragma unroll
            for (int i = 0; i < 8; i++) {
                unsigned long long ap = pack2(am[i]);
                ffma2(acc[i][0], ap, bp0);
                ffma2(acc[i][1], ap, bp1);
                ffma2(acc[i][2], ap, bp2);
                ffma2(acc[i][3], ap, bp3);
            }
        }
    }

    float bcol[8];
#pragma unroll
    for (int j = 0; j < 8; j++) bcol[j] = bias[bn + n0 + j];
#pragma unroll
    for (int i = 0; i < 8; i++) {
        float* crow = C + (bm + m0 + i) * (size_t)ldc + bn + n0;
#pragma unroll
        for (int j = 0; j < 4; j++) {
            float lo = __uint_as_float((unsigned)(acc[i][j] & 0xffffffffull)) + bcol[2 * j];
            float hi = __uint_as_float((unsigned)(acc[i][j] >> 32)) + bcol[2 * j + 1];
            if (RELU) { lo = fmaxf(lo, 0.f); hi = fmaxf(hi, 0.f); }
            crow[2 * j]     = lo;
            crow[2 * j + 1] = hi;
        }
    }
}

// ---------------------------------------------------------------------------
// Pack Wkv = [Wk ; Wv] (512 x 256), bkv = [bk ; bv]
// ---------------------------------------------------------------------------
__global__ void pack_wkv_kernel(const float* __restrict__ Wk, const float* __restrict__ bk,
                                const float* __restrict__ Wv, const float* __restrict__ bv,
                                float* __restrict__ Wkv, float* __restrict__ bkv)
{
    const int nrow = blockIdx.x;
    const int t    = threadIdx.x;
    const float* src = (nrow < DOUT) ? (Wk + (size_t)nrow * DIN)
                                     : (Wv + (size_t)(nrow - DOUT) * DIN);
    Wkv[(size_t)nrow * DIN + t] = src[t];
    if (t == 0) bkv[nrow] = (nrow < DOUT) ? bk[nrow] : bv[nrow - DOUT];
}

// ---------------------------------------------------------------------------
// Row sums of neighbor_inputs (for the exact ==0 padding mask)
// 8 rows per CTA, one warp per row.
// ---------------------------------------------------------------------------
__global__ void __launch_bounds__(256)
rowsum_kernel(const float* __restrict__ X, float* __restrict__ rs)
{
    const int row  = blockIdx.x * 8 + (threadIdx.x >> 5);
    const int lane = threadIdx.x & 31;
    const float4* p = (const float4*)(X + (size_t)row * DIN) + lane * 2;
    float4 v0 = p[0], v1 = p[1];
    float s = v0.x + v0.y + v0.z + v0.w + v1.x + v1.y + v1.z + v1.w;
#pragma unroll
    for (int o = 16; o; o >>= 1) s += __shfl_xor_sync(0xffffffffu, s, o);
    if (lane == 0) rs[row] = s;
}

// ---------------------------------------------------------------------------
// Fused attention: energies -> mask -> softmax -> context, one node per CTA
// ---------------------------------------------------------------------------
__global__ void __launch_bounds__(256)
attn_kernel(const float* __restrict__ Q, const float* __restrict__ KV,
            const float* __restrict__ rowsum, float* __restrict__ ctx)
{
    __shared__ float qs[256];
    __shared__ float es[32];
    __shared__ float att[32];
    const int n    = blockIdx.x;
    const int t    = threadIdx.x;
    const int lane = t & 31, w = t >> 5;

    qs[t] = Q[(size_t)n * DOUT + t];
    __syncthreads();

    // energies: 8 warps x 4 neighbors each
#pragma unroll
    for (int i = 0; i < 4; i++) {
        const int k = w * 4 + i;
        const float* kr = KV + ((size_t)n * KNBR + k) * DCAT + lane * 8;
        float4 k0 = *(const float4*)kr;
        float4 k1 = *(const float4*)(kr + 4);
        const float* qp = qs + lane * 8;
        float p = k0.x * qp[0] + k0.y * qp[1] + k0.z * qp[2] + k0.w * qp[3]
                + k1.x * qp[4] + k1.y * qp[5] + k1.z * qp[6] + k1.w * qp[7];
#pragma unroll
        for (int o = 16; o; o >>= 1) p += __shfl_xor_sync(0xffffffffu, p, o);
        if (lane == 0) es[k] = p;
    }
    __syncthreads();

    // softmax over K=32 (warp 0), masked positions forced to 1e-12 pre-softmax
    if (t < 32) {
        float e = es[t];
        if (rowsum[(size_t)n * KNBR + t] == 0.0f) e = 1e-12f;
        float m = e;
#pragma unroll
        for (int o = 16; o; o >>= 1) m = fmaxf(m, __shfl_xor_sync(0xffffffffu, m, o));
        float ex = expf(e - m);
        float s = ex;
#pragma unroll
        for (int o = 16; o; o >>= 1) s += __shfl_xor_sync(0xffffffffu, s, o);
        att[t] = ex / s;
    }
    __syncthreads();

    // context[d] = sum_k att[k] * values[n,k,d]   (values = KV cols 256..511)
    const float* vb = KV + (size_t)n * KNBR * DCAT + DOUT + t;
    float c = 0.f;
#pragma unroll
    for (int k = 0; k < KNBR; k++) c = fmaf(att[k], vb[(size_t)k * DCAT], c);
    ctx[(size_t)n * DOUT + t] = c;
}

// ---------------------------------------------------------------------------
// BatchNorm statistics: two-phase deterministic reduction
// ---------------------------------------------------------------------------
__global__ void __launch_bounds__(256)
bn_partial_kernel(const float* __restrict__ ob, float* __restrict__ psum,
                  float* __restrict__ psq)
{
    const int b = blockIdx.x, t = threadIdx.x;  // 128 blocks x 128 rows each
    float s0 = 0, s1 = 0, q0 = 0, q1 = 0;
    for (int r = 0; r < 128; r++) {
        const float* row = ob + ((size_t)b * 128 + r) * DCAT;
        float x0 = row[t], x1 = row[t + 256];
        s0 += x0; q0 += x0 * x0;
        s1 += x1; q1 += x1 * x1;
    }
    psum[b * DCAT + t]       = s0;
    psum[b * DCAT + t + 256] = s1;
    psq[b * DCAT + t]        = q0;
    psq[b * DCAT + t + 256]  = q1;
}

__global__ void bn_final_kernel(const float* __restrict__ psum, const float* __restrict__ psq,
                                float* __restrict__ mean, float* __restrict__ rstd)
{
    const int c = blockIdx.x * 256 + threadIdx.x;
    float s = 0, q = 0;
    for (int b = 0; b < 128; b++) { s += psum[b * DCAT + c]; q += psq[b * DCAT + c]; }
    float m = s / (float)N_NODES;
    float v = q / (float)N_NODES - m * m;   // biased variance (ddof=0)
    mean[c] = m;
    rstd[c] = rsqrtf(v + 1e-5f);
}

// ---------------------------------------------------------------------------
// Final elementwise: out = gate * relu(gamma*(output-mean)*rstd + beta)
// ---------------------------------------------------------------------------
__global__ void __launch_bounds__(256)
final_kernel(const float* __restrict__ ob, const float* __restrict__ gate,
             const float* __restrict__ mean, const float* __restrict__ rstd,
             const float* __restrict__ gamma, const float* __restrict__ beta,
             float* __restrict__ out)
{
    const size_t i = (size_t)blockIdx.x * 256 + threadIdx.x;   // float4 index
    const int    c = ((int)(i & 127)) * 4;
    float4 x = ((const float4*)ob)[i];
    float4 g = ((const float4*)gate)[i];
    float4 r;
    r.x = g.x * fmaxf(gamma[c + 0] * (x.x - mean[c + 0]) * rstd[c + 0] + beta[c + 0], 0.f);
    r.y = g.y * fmaxf(gamma[c + 1] * (x.y - mean[c + 1]) * rstd[c + 1] + beta[c + 1], 0.f);
    r.z = g.z * fmaxf(gamma[c + 2] * (x.z - mean[c + 2]) * rstd[c + 2] + beta[c + 2], 0.f);
    r.w = g.w * fmaxf(gamma[c + 3] * (x.w - mean[c + 3]) * rstd[c + 3] + beta[c + 3], 0.f);
    ((float4*)out)[i] = r;
}

// ---------------------------------------------------------------------------
// Launch
// ---------------------------------------------------------------------------
extern "C" void kernel_launch(void* const* d_in, const int* in_sizes, int n_in,
                              void* d_out, int out_size)
{
    const float* input = (const float*)d_in[0];
    const float* nbr   = (const float*)d_in[1];
    const float* Wq    = (const float*)d_in[2];
    const float* bq    = (const float*)d_in[3];
    const float* Wk    = (const float*)d_in[4];
    const float* bk    = (const float*)d_in[5];
    const float* Wv    = (const float*)d_in[6];
    const float* bv    = (const float*)d_in[7];
    const float* Wno   = (const float*)d_in[8];
    const float* bno   = (const float*)d_in[9];
    const float* Wio   = (const float*)d_in[10];
    const float* bio   = (const float*)d_in[11];
    const float* Wg    = (const float*)d_in[12];
    const float* bg    = (const float*)d_in[13];
    const float* gamma = (const float*)d_in[14];
    const float* beta  = (const float*)d_in[15];
    float* out = (float*)d_out;

    float *Qp, *KVp, *rsp, *ctxp, *obp, *gatep, *Wkvp, *bkvp, *psump, *psqp, *meanp, *rstdp;
    cudaGetSymbolAddress((void**)&Qp,    g_Q);
    cudaGetSymbolAddress((void**)&KVp,   g_KV);
    cudaGetSymbolAddress((void**)&rsp,   g_rowsum);
    cudaGetSymbolAddress((void**)&ctxp,  g_ctx);
    cudaGetSymbolAddress((void**)&obp,   g_ob);
    cudaGetSymbolAddress((void**)&gatep, g_gate);
    cudaGetSymbolAddress((void**)&Wkvp,  g_Wkv);
    cudaGetSymbolAddress((void**)&bkvp,  g_bkv);
    cudaGetSymbolAddress((void**)&psump, g_psum);
    cudaGetSymbolAddress((void**)&psqp,  g_psq);
    cudaGetSymbolAddress((void**)&meanp, g_mean);
    cudaGetSymbolAddress((void**)&rstdp, g_rstd);

    // Independent prep
    pack_wkv_kernel<<<DCAT, 256>>>(Wk, bk, Wv, bv, Wkvp, bkvp);
    rowsum_kernel<<<NROWS / 8, 256>>>(nbr, rsp);

    // queries = input @ Wq^T + bq
    sgemm_kernel<false><<<dim3(DOUT / 128, N_NODES / 128), 256>>>(input, Wq, bq, Qp, DIN, DOUT);
    // self_out = input @ Wio^T + bio  -> output[:, 0:256]
    sgemm_kernel<false><<<dim3(DOUT / 128, N_NODES / 128), 256>>>(input, Wio, bio, obp, DIN, DCAT);

    // keys|values = neighbor_inputs @ [Wk;Wv]^T + [bk;bv]   (the heavy GEMM)
    sgemm_kernel<false><<<dim3(DCAT / 128, NROWS / 128), 256>>>(nbr, Wkvp, bkvp, KVp, DIN, DCAT);

    // attention: energies -> mask -> softmax -> context
    attn_kernel<<<N_NODES, 256>>>(Qp, KVp, rsp, ctxp);

    // neigh_out = context @ Wno^T + bno -> output[:, 256:512]
    sgemm_kernel<false><<<dim3(DOUT / 128, N_NODES / 128), 256>>>(ctxp, Wno, bno, obp + 256, DOUT, DCAT);

    // gate = relu(output @ Wg^T + bg)
    sgemm_kernel<true><<<dim3(DCAT / 128, N_NODES / 128), 256>>>(obp, Wg, bg, gatep, DCAT, DCAT);

    // BatchNorm statistics (deterministic two-phase) + final elementwise
    bn_partial_kernel<<<128, 256>>>(obp, psump, psqp);
    bn_final_kernel<<<2, 256>>>(psump, psqp, meanp, rstdp);
    final_kernel<<<(N_NODES * DCAT / 4) / 256, 256>>>(obp, gatep, meanp, rstdp, gamma, beta, out);
}